// round 2
// baseline (speedup 1.0000x reference)
#include <cuda_runtime.h>
#include <cuda_bf16.h>
#include <math.h>

// ---------------------------------------------------------------------------
// Actor_10505490006716 — MTRNN actor, pruned dataflow (cell1 @ t=2,3 is dead):
//   gates0/1 = [x0;x1] @ Wih1^T + b1          (8192 x 2048 x K=3072)
//   h1,c1    = cell(gates0, c=0), relu
//   gates1  += h1 @ Whh1^T
//   h1       = cell(gates1, c1), relu
//   h2 = cellz(h1 @ Wih2^T + b2); h3 = cellz(h2 @ Wih3^T + b3)
//   h4 = cellz(h3 @ Wih4^T + b4)
//   out = (u < relu(h4 @ Wout^T + bout)) ? 1 : 0
//
// Round 2: SGEMM inner loop converted to packed fp32 FFMA2 (PTX fma.rn.f32x2),
// doubling the fp32 FMA ceiling (FFMA-3reg is rt=2/SMSP; FFMA2 gives 2 lanes
// per issue). A operand stored pre-duplicated in smem; double-buffered BK=8.
// Accumulation order per output element unchanged -> bit-identical numerics.
// ---------------------------------------------------------------------------

#define BATCH 4096
#define HID   512
#define G4    2048            // 4*H
#define INDIM 3072
#define ACT   512

// scratch (device globals: allocation-free per harness rules)
__device__ float g_X[(size_t)8192 * 3072];     // packed [x_t0 ; x_t1]
__device__ float g_G[(size_t)8192 * 2048];     // gates (t0 rows, t1 rows)
__device__ float g_h1[(size_t)BATCH * HID];
__device__ float g_c1[(size_t)BATCH * HID];
__device__ float g_hA[(size_t)BATCH * HID];
__device__ float g_hB[(size_t)BATCH * HID];

// ---------------------------------------------------------------------------
__global__ void pack_x_kernel(const float* __restrict__ state,
                              const float* __restrict__ goal,
                              float* __restrict__ X)
{
    const int COL4 = INDIM / 4;                     // 768
    size_t idx = (size_t)blockIdx.x * blockDim.x + threadIdx.x;
    if (idx >= (size_t)8192 * COL4) return;
    int row  = (int)(idx / COL4);
    int col  = (int)(idx % COL4) * 4;
    int b    = row & 4095;
    int t    = row >> 12;                           // 0 or 1
    float4 v;
    if (col < 2048) {
        v = *(const float4*)(state + ((size_t)(b * 4 + t)) * 2048 + col);
    } else {
        v = *(const float4*)(goal + ((size_t)(b * 4 + t)) * 1024 + (col - 2048));
    }
    *(float4*)(X + (size_t)row * INDIM + col) = v;
}

// ---------------------------------------------------------------------------
// packed fp32 helpers
// ---------------------------------------------------------------------------
__device__ __forceinline__ unsigned long long pack2dup(float v) {
    unsigned long long r;
    asm("mov.b64 %0, {%1, %1};" : "=l"(r) : "f"(v));
    return r;
}
#define FMA2(d, a, b) \
    asm("fma.rn.f32x2 %0, %1, %2, %3;" : "=l"(d) : "l"(a), "l"(b), "l"(d))
#define UNPACK2(lo, hi, v) \
    asm("mov.b64 {%0, %1}, %2;" : "=f"(lo), "=f"(hi) : "l"(v))

// ---------------------------------------------------------------------------
// SGEMM (NT): C[M,N] = A[M,K] * B[N,K]^T   (+ epilogue per mode)
//   mode 0: C = acc + bias1[n] (+ bias2[n])
//   mode 1: C += acc
//   mode 2: Out[m,n] = (U[m,n] < max(acc + bias1[n], 0)) ? 1 : 0
// BM=BN=128, BK=8, 256 threads, 8x8 per thread via 8x4 f32x2 accumulators.
// ---------------------------------------------------------------------------
#define BM 128
#define BN 128
#define BK 8

__global__ void __launch_bounds__(256, 2)
sgemm_nt(const float* __restrict__ A, const float* __restrict__ B,
         float* __restrict__ C,
         const float* __restrict__ bias1, const float* __restrict__ bias2,
         const float* __restrict__ U, float* __restrict__ Out,
         int M, int N, int K, int mode)
{
    // A stored duplicated: As2[k][m] = (a, a) as packed f32x2
    __shared__ __align__(16) unsigned long long As2[2][BK][BM + 4];
    __shared__ __align__(16) float              Bs [2][BK][BN + 4];

    const int bm  = blockIdx.y * BM;
    const int bn  = blockIdx.x * BN;
    const int tid = threadIdx.x;
    const int tx  = tid & 15;
    const int ty  = tid >> 4;

    const int lr = tid >> 1;          // 0..127
    const int lc = (tid & 1) << 2;    // 0 or 4

    const float* Ap = A + (size_t)(bm + lr) * K + lc;
    const float* Bp = B + (size_t)(bn + lr) * K + lc;

    unsigned long long acc[8][4];
#pragma unroll
    for (int i = 0; i < 8; i++)
#pragma unroll
        for (int j = 0; j < 4; j++) acc[i][j] = 0ULL;

    // preload tile 0
    float4 a = *(const float4*)Ap;
    float4 b = *(const float4*)Bp;
    As2[0][lc + 0][lr] = pack2dup(a.x);
    As2[0][lc + 1][lr] = pack2dup(a.y);
    As2[0][lc + 2][lr] = pack2dup(a.z);
    As2[0][lc + 3][lr] = pack2dup(a.w);
    Bs [0][lc + 0][lr] = b.x;
    Bs [0][lc + 1][lr] = b.y;
    Bs [0][lc + 2][lr] = b.z;
    Bs [0][lc + 3][lr] = b.w;
    __syncthreads();

    const int nk = K / BK;
    for (int t = 0; t < nk; t++) {
        const int cur = t & 1;
        if (t + 1 < nk) {
            a = *(const float4*)(Ap + (t + 1) * BK);
            b = *(const float4*)(Bp + (t + 1) * BK);
        }
#pragma unroll
        for (int kk = 0; kk < BK; kk++) {
            const unsigned long long* arow = &As2[cur][kk][ty * 8];
            ulonglong2 av0 = *(const ulonglong2*)(arow + 0);
            ulonglong2 av1 = *(const ulonglong2*)(arow + 2);
            ulonglong2 av2 = *(const ulonglong2*)(arow + 4);
            ulonglong2 av3 = *(const ulonglong2*)(arow + 6);
            const float* brow = &Bs[cur][kk][tx * 8];
            ulonglong2 bv0 = *(const ulonglong2*)(brow + 0);
            ulonglong2 bv1 = *(const ulonglong2*)(brow + 4);
            unsigned long long a2[8] = {av0.x, av0.y, av1.x, av1.y,
                                        av2.x, av2.y, av3.x, av3.y};
            unsigned long long b2[4] = {bv0.x, bv0.y, bv1.x, bv1.y};
#pragma unroll
            for (int i = 0; i < 8; i++)
#pragma unroll
                for (int j = 0; j < 4; j++)
                    FMA2(acc[i][j], a2[i], b2[j]);
        }
        if (t + 1 < nk) {
            const int nxt = cur ^ 1;
            As2[nxt][lc + 0][lr] = pack2dup(a.x);
            As2[nxt][lc + 1][lr] = pack2dup(a.y);
            As2[nxt][lc + 2][lr] = pack2dup(a.z);
            As2[nxt][lc + 3][lr] = pack2dup(a.w);
            Bs [nxt][lc + 0][lr] = b.x;
            Bs [nxt][lc + 1][lr] = b.y;
            Bs [nxt][lc + 2][lr] = b.z;
            Bs [nxt][lc + 3][lr] = b.w;
        }
        __syncthreads();
    }

    // unpack accumulators
    float accf[8][8];
#pragma unroll
    for (int i = 0; i < 8; i++)
#pragma unroll
        for (int j = 0; j < 4; j++)
            UNPACK2(accf[i][2 * j], accf[i][2 * j + 1], acc[i][j]);

    const int row0 = bm + ty * 8;
    const int col0 = bn + tx * 8;

    if (mode == 0) {
        float bv[8];
#pragma unroll
        for (int j = 0; j < 8; j++) {
            bv[j] = bias1[col0 + j];
            if (bias2) bv[j] += bias2[col0 + j];
        }
#pragma unroll
        for (int i = 0; i < 8; i++) {
            float* Cp = C + (size_t)(row0 + i) * N + col0;
#pragma unroll
            for (int j = 0; j < 8; j++) Cp[j] = accf[i][j] + bv[j];
        }
    } else if (mode == 1) {
#pragma unroll
        for (int i = 0; i < 8; i++) {
            float* Cp = C + (size_t)(row0 + i) * N + col0;
#pragma unroll
            for (int j = 0; j < 8; j++) Cp[j] += accf[i][j];
        }
    } else {
        float bv[8];
#pragma unroll
        for (int j = 0; j < 8; j++) bv[j] = bias1[col0 + j];
#pragma unroll
        for (int i = 0; i < 8; i++) {
            const float* Up = U + (size_t)(row0 + i) * N + col0;
            float* Op = Out + (size_t)(row0 + i) * N + col0;
#pragma unroll
            for (int j = 0; j < 8; j++) {
                float p = fmaxf(accf[i][j] + bv[j], 0.f);
                Op[j] = (Up[j] < p) ? 1.0f : 0.0f;
            }
        }
    }
}

// ---------------------------------------------------------------------------
// LSTM cell elementwise epilogues. gates row layout: [i | f | g | o], 512 each.
// ---------------------------------------------------------------------------
__device__ __forceinline__ float sigm(float x) { return 1.0f / (1.0f + expf(-x)); }

__global__ void cell_zero_kernel(const float* __restrict__ gates,
                                 float* __restrict__ h,
                                 float* __restrict__ c /* nullable */)
{
    int idx = blockIdx.x * 256 + threadIdx.x;
    if (idx >= BATCH * HID) return;
    int m = idx >> 9;
    int n = idx & 511;
    const float* gr = gates + (size_t)m * G4;
    float gi = gr[n];
    float gg = gr[n + 1024];
    float go = gr[n + 1536];
    float cn = sigm(gi) * tanhf(gg);
    float hn = sigm(go) * tanhf(cn);
    h[idx] = fmaxf(hn, 0.f);
    if (c) c[idx] = fmaxf(cn, 0.f);
}

__global__ void cell_step_kernel(const float* __restrict__ gates,
                                 const float* __restrict__ cprev,
                                 float* __restrict__ h)
{
    int idx = blockIdx.x * 256 + threadIdx.x;
    if (idx >= BATCH * HID) return;
    int m = idx >> 9;
    int n = idx & 511;
    const float* gr = gates + (size_t)m * G4;
    float gi = gr[n];
    float gf = gr[n + 512];
    float gg = gr[n + 1024];
    float go = gr[n + 1536];
    float cn = sigm(gf) * cprev[idx] + sigm(gi) * tanhf(gg);
    float hn = sigm(go) * tanhf(cn);
    h[idx] = fmaxf(hn, 0.f);
}

// ---------------------------------------------------------------------------
extern "C" void kernel_launch(void* const* d_in, const int* in_sizes, int n_in,
                              void* d_out, int out_size)
{
    const float* state = (const float*)d_in[0];
    const float* goal  = (const float*)d_in[1];
    const float* u     = (const float*)d_in[2];
    const float* Wih1  = (const float*)d_in[3];
    const float* Whh1  = (const float*)d_in[4];
    const float* bih1  = (const float*)d_in[5];
    const float* bhh1  = (const float*)d_in[6];
    const float* Wih2  = (const float*)d_in[7];
    const float* bih2  = (const float*)d_in[9];
    const float* bhh2  = (const float*)d_in[10];
    const float* Wih3  = (const float*)d_in[11];
    const float* bih3  = (const float*)d_in[13];
    const float* bhh3  = (const float*)d_in[14];
    const float* Wih4  = (const float*)d_in[15];
    const float* bih4  = (const float*)d_in[17];
    const float* bhh4  = (const float*)d_in[18];
    const float* Wout  = (const float*)d_in[19];
    const float* bout  = (const float*)d_in[20];
    float* out = (float*)d_out;

    float *X, *G, *h1, *c1, *hA, *hB;
    cudaGetSymbolAddress((void**)&X,  g_X);
    cudaGetSymbolAddress((void**)&G,  g_G);
    cudaGetSymbolAddress((void**)&h1, g_h1);
    cudaGetSymbolAddress((void**)&c1, g_c1);
    cudaGetSymbolAddress((void**)&hA, g_hA);
    cudaGetSymbolAddress((void**)&hB, g_hB);

    float* G1 = G + (size_t)4096 * 2048;   // t=1 gate rows

    // pack x0,x1
    {
        size_t total = (size_t)8192 * (INDIM / 4);
        int blocks = (int)((total + 255) / 256);
        pack_x_kernel<<<blocks, 256>>>(state, goal, X);
    }

    // big GEMM: gates(t0,t1) = X @ Wih1^T + (bih1+bhh1)
    sgemm_nt<<<dim3(G4 / BN, 8192 / BM), 256>>>(
        X, Wih1, G, bih1, bhh1, nullptr, nullptr, 8192, G4, INDIM, 0);

    // cell1 @ t=0
    cell_zero_kernel<<<(BATCH * HID) / 256, 256>>>(G, h1, c1);

    // gates(t1) += h1 @ Whh1^T
    sgemm_nt<<<dim3(G4 / BN, BATCH / BM), 256>>>(
        h1, Whh1, G1, nullptr, nullptr, nullptr, nullptr, BATCH, G4, HID, 1);

    // cell1 @ t=1 (overwrites h1)
    cell_step_kernel<<<(BATCH * HID) / 256, 256>>>(G1, c1, h1);

    // layer 2
    sgemm_nt<<<dim3(G4 / BN, BATCH / BM), 256>>>(
        h1, Wih2, G, bih2, bhh2, nullptr, nullptr, BATCH, G4, HID, 0);
    cell_zero_kernel<<<(BATCH * HID) / 256, 256>>>(G, hA, nullptr);

    // layer 3
    sgemm_nt<<<dim3(G4 / BN, BATCH / BM), 256>>>(
        hA, Wih3, G, bih3, bhh3, nullptr, nullptr, BATCH, G4, HID, 0);
    cell_zero_kernel<<<(BATCH * HID) / 256, 256>>>(G, hB, nullptr);

    // layer 4
    sgemm_nt<<<dim3(G4 / BN, BATCH / BM), 256>>>(
        hB, Wih4, G, bih4, bhh4, nullptr, nullptr, BATCH, G4, HID, 0);
    cell_zero_kernel<<<(BATCH * HID) / 256, 256>>>(G, hA, nullptr);

    // output head: out = (u < relu(hA @ Wout^T + bout))
    sgemm_nt<<<dim3(ACT / BN, BATCH / BM), 256>>>(
        hA, Wout, nullptr, bout, nullptr, u, out, BATCH, ACT, HID, 2);
}

// round 4
// speedup vs baseline: 1.6330x; 1.6330x over previous
#include <cuda_runtime.h>
#include <cuda_bf16.h>
#include <math.h>
#include <stdint.h>

// ===========================================================================
// Actor_10505490006716 — HMMA (mma.sync bf16) with 3-plane fp32 split.
// tcgen05 is unavailable (harness PTX target = compute_103, no 'a' features);
// mma.sync/ldmatrix/cp.async are base features and compile fine.
//
// Pruned dataflow (cell1 @ t=2,3 dead):
//   G[0:8192)   = [x0;x1] @ Wih1^T + b1       (M=8192, N=2048, K=3072)
//   h1,c1       = cell(G_t0, 0), relu
//   G_t1       += h1 @ Whh1^T                 (M=4096, N=2048, K=512)
//   h1          = cell(G_t1, c1), relu
//   h2..h4 chain (K=512), head: out = (u < relu(h4 @ Wout^T + bout))
// Every fp32 operand split into 3 bf16 planes; 6 plane-products accumulated
// in fp32 register accumulators -> ~fp32 accuracy on tensor cores.
// ===========================================================================

#define BATCH 4096
#define HID   512
#define G4    2048
#define INDIM 3072

__device__ __nv_bfloat16 g_XA [(size_t)3 * 8192 * 3072];
__device__ __nv_bfloat16 g_W1 [(size_t)3 * 2048 * 3072];
__device__ __nv_bfloat16 g_Whh[(size_t)3 * 2048 * 512];
__device__ __nv_bfloat16 g_W2 [(size_t)3 * 2048 * 512];
__device__ __nv_bfloat16 g_W3 [(size_t)3 * 2048 * 512];
__device__ __nv_bfloat16 g_W4 [(size_t)3 * 2048 * 512];
__device__ __nv_bfloat16 g_Wo [(size_t)3 * 512 * 512];
__device__ __nv_bfloat16 g_Hs [(size_t)3 * 4096 * 512];
__device__ float g_G [(size_t)8192 * 2048];
__device__ float g_c1[(size_t)4096 * 512];

// ---- PTX helpers (all base-arch features) ----------------------------------
__device__ __forceinline__ uint32_t smem_u32(const void* p) {
    uint32_t a;
    asm("{ .reg .u64 t; cvta.to.shared.u64 t, %1; cvt.u32.u64 %0, t; }"
        : "=r"(a) : "l"(p));
    return a;
}
__device__ __forceinline__ void cp16(uint32_t dst, const void* src) {
    asm volatile("cp.async.cg.shared.global [%0], [%1], 16;"
                 :: "r"(dst), "l"(src));
}
#define CP_COMMIT() asm volatile("cp.async.commit_group;" ::: "memory")
#define CP_WAIT1()  asm volatile("cp.async.wait_group 1;" ::: "memory")

__device__ __forceinline__ void ldsm_x4(uint32_t& r0, uint32_t& r1,
                                        uint32_t& r2, uint32_t& r3,
                                        uint32_t addr) {
    asm volatile("ldmatrix.sync.aligned.m8n8.x4.shared.b16 {%0,%1,%2,%3}, [%4];"
                 : "=r"(r0), "=r"(r1), "=r"(r2), "=r"(r3) : "r"(addr));
}
__device__ __forceinline__ void mma16816(float* d, const uint32_t* a,
                                         const uint32_t* b) {
    asm volatile("mma.sync.aligned.m16n8k16.row.col.f32.bf16.bf16.f32 "
                 "{%0,%1,%2,%3}, {%4,%5,%6,%7}, {%8,%9}, {%0,%1,%2,%3};"
                 : "+f"(d[0]), "+f"(d[1]), "+f"(d[2]), "+f"(d[3])
                 : "r"(a[0]), "r"(a[1]), "r"(a[2]), "r"(a[3]),
                   "r"(b[0]), "r"(b[1]));
}
__device__ __forceinline__ uint32_t swz(uint32_t off) {
    return off ^ ((off >> 3) & 0x70);
}

// ---- splitting --------------------------------------------------------------
__device__ __forceinline__ void split3(float a, __nv_bfloat16& o0,
                                       __nv_bfloat16& o1, __nv_bfloat16& o2) {
    __nv_bfloat16 b0 = __float2bfloat16_rn(a);
    float r = a - __bfloat162float(b0);
    __nv_bfloat16 b1 = __float2bfloat16_rn(r);
    float r2 = r - __bfloat162float(b1);
    o0 = b0; o1 = b1; o2 = __float2bfloat16_rn(r2);
}

__global__ void split_x_kernel(const float* __restrict__ state,
                               const float* __restrict__ goal,
                               __nv_bfloat16* __restrict__ P, size_t S)
{
    size_t idx = (size_t)blockIdx.x * 256 + threadIdx.x;
    if (idx >= (size_t)8192 * INDIM) return;
    int row = (int)(idx / INDIM);
    int col = (int)(idx % INDIM);
    int b = row & 4095, t = row >> 12;
    float v = (col < 2048) ? state[(size_t)(b * 4 + t) * 2048 + col]
                           : goal [(size_t)(b * 4 + t) * 1024 + (col - 2048)];
    __nv_bfloat16 a0, a1, a2; split3(v, a0, a1, a2);
    P[idx] = a0; P[idx + S] = a1; P[idx + 2 * S] = a2;
}

__global__ void split_w_kernel(const float* __restrict__ src,
                               __nv_bfloat16* __restrict__ P, size_t S, size_t n)
{
    size_t idx = (size_t)blockIdx.x * 256 + threadIdx.x;
    if (idx >= n) return;
    __nv_bfloat16 a0, a1, a2; split3(src[idx], a0, a1, a2);
    P[idx] = a0; P[idx + S] = a1; P[idx + 2 * S] = a2;
}

// ---- LSTM cell epilogues ----------------------------------------------------
__device__ __forceinline__ float sigm(float x) { return 1.0f / (1.0f + expf(-x)); }

__global__ void cell_zero_kernel(const float* __restrict__ gates,
                                 __nv_bfloat16* __restrict__ HP, size_t S,
                                 float* __restrict__ c)
{
    int idx = blockIdx.x * 256 + threadIdx.x;
    if (idx >= BATCH * HID) return;
    int m = idx >> 9, n = idx & 511;
    const float* gr = gates + (size_t)m * G4;
    float cn = sigm(gr[n]) * tanhf(gr[n + 1024]);
    float hn = fmaxf(sigm(gr[n + 1536]) * tanhf(cn), 0.f);
    __nv_bfloat16 a0, a1, a2; split3(hn, a0, a1, a2);
    HP[idx] = a0; HP[idx + S] = a1; HP[idx + 2 * S] = a2;
    if (c) c[idx] = fmaxf(cn, 0.f);
}

__global__ void cell_step_kernel(const float* __restrict__ gates,
                                 const float* __restrict__ cprev,
                                 __nv_bfloat16* __restrict__ HP, size_t S)
{
    int idx = blockIdx.x * 256 + threadIdx.x;
    if (idx >= BATCH * HID) return;
    int m = idx >> 9, n = idx & 511;
    const float* gr = gates + (size_t)m * G4;
    float cn = sigm(gr[n + 512]) * cprev[idx] + sigm(gr[n]) * tanhf(gr[n + 1024]);
    float hn = fmaxf(sigm(gr[n + 1536]) * tanhf(cn), 0.f);
    __nv_bfloat16 a0, a1, a2; split3(hn, a0, a1, a2);
    HP[idx] = a0; HP[idx + S] = a1; HP[idx + 2 * S] = a2;
}

// ===========================================================================
// HMMA GEMM: C[M,N](fp32) = sum over 6 plane products of Ai[M,K] * Bj[N,K]^T
// CTA tile 128x128, K-chunk 64 bf16 (128B rows), 3-stage cp.async pipeline,
// 8 warps each 32(m) x 64(n). Smallest plane products accumulated first.
//   mode 0: C = acc + bias1[n] (+bias2[n]); mode 1: C += acc;
//   mode 2: Out = (U < relu(acc + bias1[n])) ? 1 : 0
// ===========================================================================
#define STAGE_BYTES 32768          // A 16KB + B 16KB
#define NSTAGE 3
#define GSMEM  (NSTAGE * STAGE_BYTES)

__global__ void __launch_bounds__(256, 2)
mma_gemm(const __nv_bfloat16* __restrict__ Ap, size_t aPlane,
         const __nv_bfloat16* __restrict__ Bp, size_t bPlane,
         float* __restrict__ C,
         const float* __restrict__ bias1, const float* __restrict__ bias2,
         const float* __restrict__ U, float* __restrict__ Out,
         int M, int N, int K, int mode)
{
    extern __shared__ __align__(1024) char smem[];
    const uint32_t smb = smem_u32(smem);
    const int tid  = threadIdx.x;
    const int lane = tid & 31;
    const int wid  = tid >> 5;
    const int wm   = wid & 3;        // 4 warps over M (32 rows each)
    const int wn   = wid >> 2;       // 2 warps over N (64 cols each)
    const int bm   = blockIdx.y * 128;
    const int bn   = blockIdx.x * 128;

    // plane-product order: smallest first
    const int PA[6] = {2, 0, 1, 1, 0, 0};
    const int PB[6] = {0, 2, 1, 0, 1, 0};

    const __nv_bfloat16* Ab[6];
    const __nv_bfloat16* Bb[6];
#pragma unroll
    for (int p = 0; p < 6; p++) {
        Ab[p] = Ap + (size_t)PA[p] * aPlane + (size_t)bm * K;
        Bb[p] = Bp + (size_t)PB[p] * bPlane + (size_t)bn * K;
    }

    const int kper = K >> 6;          // chunks per product
    const int NCH  = 6 * kper;

    // loader: thread handles 4 x 16B units for A and 4 for B per chunk
    const int lrow = tid >> 3;        // base row pattern
    const int lcu  = tid & 7;
    auto issue = [&](int c) {
        if (c < NCH) {
            int pr = c / kper;
            int kc = c - pr * kper;
            const __nv_bfloat16* As = Ab[pr] + kc * 64;
            const __nv_bfloat16* Bs = Bb[pr] + kc * 64;
            uint32_t sb = smb + (c % NSTAGE) * STAGE_BYTES;
#pragma unroll
            for (int i = 0; i < 4; i++) {
                int row = lrow + i * 32;
                uint32_t off = swz((uint32_t)(row * 128 + lcu * 16));
                cp16(sb + off, As + (size_t)row * K + lcu * 8);
                cp16(sb + 16384 + off, Bs + (size_t)row * K + lcu * 8);
            }
        }
        CP_COMMIT();
    };

    float acc[2][8][4];
#pragma unroll
    for (int i = 0; i < 2; i++)
#pragma unroll
        for (int j = 0; j < 8; j++)
#pragma unroll
            for (int v = 0; v < 4; v++) acc[i][j][v] = 0.f;

    issue(0);
    issue(1);

    // precomputed ldmatrix lane-address components
    const int a_row = wm * 32 + (lane & 7) + ((lane >> 3) & 1) * 8;
    const int a_kb  = ((lane >> 4) & 1) * 16;
    const int b_row = wn * 64 + (lane & 7) + ((lane >> 4) & 1) * 8;
    const int b_kb  = ((lane >> 3) & 1) * 16;

    for (int c = 0; c < NCH; c++) {
        CP_WAIT1();
        __syncthreads();
        issue(c + 2);

        uint32_t sA = smb + (c % NSTAGE) * STAGE_BYTES;
        uint32_t sB = sA + 16384;

#pragma unroll
        for (int ks = 0; ks < 4; ks++) {
            uint32_t a[2][4];
#pragma unroll
            for (int i = 0; i < 2; i++) {
                uint32_t off = swz((uint32_t)((a_row + i * 16) * 128 + ks * 32 + a_kb));
                ldsm_x4(a[i][0], a[i][1], a[i][2], a[i][3], sA + off);
            }
            uint32_t b[8][2];
#pragma unroll
            for (int j2 = 0; j2 < 4; j2++) {
                uint32_t off = swz((uint32_t)((b_row + j2 * 16) * 128 + ks * 32 + b_kb));
                ldsm_x4(b[2 * j2][0], b[2 * j2][1], b[2 * j2 + 1][0],
                        b[2 * j2 + 1][1], sB + off);
            }
#pragma unroll
            for (int i = 0; i < 2; i++)
#pragma unroll
                for (int j = 0; j < 8; j++)
                    mma16816(acc[i][j], a[i], b[j]);
        }
        __syncthreads();
    }

    // ---- epilogue ----
    const int r0    = bm + wm * 32 + (lane >> 2);
    const int cbase = bn + wn * 64 + (lane & 3) * 2;

#pragma unroll
    for (int i = 0; i < 2; i++) {
        const int rowA = r0 + i * 16;
#pragma unroll
        for (int j = 0; j < 8; j++) {
            const int col = cbase + j * 8;
            float v0 = acc[i][j][0], v1 = acc[i][j][1];
            float v2 = acc[i][j][2], v3 = acc[i][j][3];
            if (mode == 0) {
                float b0 = bias1[col], b1 = bias1[col + 1];
                if (bias2) { b0 += bias2[col]; b1 += bias2[col + 1]; }
                *(float2*)(C + (size_t)rowA * N + col)       = make_float2(v0 + b0, v1 + b1);
                *(float2*)(C + (size_t)(rowA + 8) * N + col) = make_float2(v2 + b0, v3 + b1);
            } else if (mode == 1) {
                float2* p0 = (float2*)(C + (size_t)rowA * N + col);
                float2* p1 = (float2*)(C + (size_t)(rowA + 8) * N + col);
                float2 o0 = *p0, o1 = *p1;
                *p0 = make_float2(o0.x + v0, o0.y + v1);
                *p1 = make_float2(o1.x + v2, o1.y + v3);
            } else {
                float b0 = bias1[col], b1 = bias1[col + 1];
                const float2 u0 = *(const float2*)(U + (size_t)rowA * N + col);
                const float2 u1 = *(const float2*)(U + (size_t)(rowA + 8) * N + col);
                float p00 = fmaxf(v0 + b0, 0.f), p01 = fmaxf(v1 + b1, 0.f);
                float p10 = fmaxf(v2 + b0, 0.f), p11 = fmaxf(v3 + b1, 0.f);
                *(float2*)(Out + (size_t)rowA * N + col) =
                    make_float2(u0.x < p00 ? 1.f : 0.f, u0.y < p01 ? 1.f : 0.f);
                *(float2*)(Out + (size_t)(rowA + 8) * N + col) =
                    make_float2(u1.x < p10 ? 1.f : 0.f, u1.y < p11 ? 1.f : 0.f);
            }
        }
    }
}

// ===========================================================================
extern "C" void kernel_launch(void* const* d_in, const int* in_sizes, int n_in,
                              void* d_out, int out_size)
{
    const float* state = (const float*)d_in[0];
    const float* goal  = (const float*)d_in[1];
    const float* u     = (const float*)d_in[2];
    const float* Wih1  = (const float*)d_in[3];
    const float* Whh1  = (const float*)d_in[4];
    const float* bih1  = (const float*)d_in[5];
    const float* bhh1  = (const float*)d_in[6];
    const float* Wih2  = (const float*)d_in[7];
    const float* bih2  = (const float*)d_in[9];
    const float* bhh2  = (const float*)d_in[10];
    const float* Wih3  = (const float*)d_in[11];
    const float* bih3  = (const float*)d_in[13];
    const float* bhh3  = (const float*)d_in[14];
    const float* Wih4  = (const float*)d_in[15];
    const float* bih4  = (const float*)d_in[17];
    const float* bhh4  = (const float*)d_in[18];
    const float* Wout  = (const float*)d_in[19];
    const float* bout  = (const float*)d_in[20];
    float* out = (float*)d_out;

    __nv_bfloat16 *XA, *W1, *Whh, *W2, *W3, *W4, *Wo, *Hs;
    float *G, *c1;
    cudaGetSymbolAddress((void**)&XA,  g_XA);
    cudaGetSymbolAddress((void**)&W1,  g_W1);
    cudaGetSymbolAddress((void**)&Whh, g_Whh);
    cudaGetSymbolAddress((void**)&W2,  g_W2);
    cudaGetSymbolAddress((void**)&W3,  g_W3);
    cudaGetSymbolAddress((void**)&W4,  g_W4);
    cudaGetSymbolAddress((void**)&Wo,  g_Wo);
    cudaGetSymbolAddress((void**)&Hs,  g_Hs);
    cudaGetSymbolAddress((void**)&G,   g_G);
    cudaGetSymbolAddress((void**)&c1,  g_c1);

    cudaFuncSetAttribute(mma_gemm, cudaFuncAttributeMaxDynamicSharedMemorySize,
                         GSMEM);

    const size_t SX  = (size_t)8192 * 3072;
    const size_t SW1 = (size_t)2048 * 3072;
    const size_t SWs = (size_t)2048 * 512;
    const size_t SWo = (size_t)512 * 512;
    const size_t SH  = (size_t)4096 * 512;
    float* G1 = G + (size_t)4096 * 2048;

    // ---- splits ----
    split_x_kernel<<<(int)((SX + 255) / 256), 256>>>(state, goal, XA, SX);
    split_w_kernel<<<(int)((SW1 + 255) / 256), 256>>>(Wih1, W1, SW1, SW1);
    split_w_kernel<<<(int)((SWs + 255) / 256), 256>>>(Whh1, Whh, SWs, SWs);
    split_w_kernel<<<(int)((SWs + 255) / 256), 256>>>(Wih2, W2, SWs, SWs);
    split_w_kernel<<<(int)((SWs + 255) / 256), 256>>>(Wih3, W3, SWs, SWs);
    split_w_kernel<<<(int)((SWs + 255) / 256), 256>>>(Wih4, W4, SWs, SWs);
    split_w_kernel<<<(int)((SWo + 255) / 256), 256>>>(Wout, Wo, SWo, SWo);

    // ---- big GEMM: G = X @ Wih1^T + (bih1 + bhh1) ----
    mma_gemm<<<dim3(2048 / 128, 8192 / 128), 256, GSMEM>>>(
        XA, SX, W1, SW1, G, bih1, bhh1, nullptr, nullptr, 8192, 2048, 3072, 0);

    cell_zero_kernel<<<(BATCH * HID) / 256, 256>>>(G, Hs, SH, c1);

    mma_gemm<<<dim3(2048 / 128, 4096 / 128), 256, GSMEM>>>(
        Hs, SH, Whh, SWs, G1, nullptr, nullptr, nullptr, nullptr, 4096, 2048, 512, 1);

    cell_step_kernel<<<(BATCH * HID) / 256, 256>>>(G1, c1, Hs, SH);

    mma_gemm<<<dim3(2048 / 128, 4096 / 128), 256, GSMEM>>>(
        Hs, SH, W2, SWs, G, bih2, bhh2, nullptr, nullptr, 4096, 2048, 512, 0);
    cell_zero_kernel<<<(BATCH * HID) / 256, 256>>>(G, Hs, SH, nullptr);

    mma_gemm<<<dim3(2048 / 128, 4096 / 128), 256, GSMEM>>>(
        Hs, SH, W3, SWs, G, bih3, bhh3, nullptr, nullptr, 4096, 2048, 512, 0);
    cell_zero_kernel<<<(BATCH * HID) / 256, 256>>>(G, Hs, SH, nullptr);

    mma_gemm<<<dim3(2048 / 128, 4096 / 128), 256, GSMEM>>>(
        Hs, SH, W4, SWs, G, bih4, bhh4, nullptr, nullptr, 4096, 2048, 512, 0);
    cell_zero_kernel<<<(BATCH * HID) / 256, 256>>>(G, Hs, SH, nullptr);

    mma_gemm<<<dim3(512 / 128, 4096 / 128), 256, GSMEM>>>(
        Hs, SH, Wo, SWo, nullptr, bout, nullptr, u, out, 4096, 512, 512, 2);
}

// round 5
// speedup vs baseline: 1.7796x; 1.0897x over previous
#include <cuda_runtime.h>
#include <cuda_bf16.h>
#include <math.h>
#include <stdint.h>

// ===========================================================================
// Actor_10505490006716 — HMMA (mma.sync bf16) with 3-plane fp32 split.
// Round 5: f-gate pruning in layers 2-4 (N=1536), vectorized split/cell
// kernels, single-sync GEMM mainloop, pre-summed biases.
// ===========================================================================

#define BATCH 4096
#define HID   512
#define G4    2048
#define INDIM 3072
#define NPRU  1536            // pruned gate width for cell_zero layers

__device__ __nv_bfloat16 g_XA [(size_t)3 * 8192 * 3072];
__device__ __nv_bfloat16 g_W1 [(size_t)3 * 2048 * 3072];
__device__ __nv_bfloat16 g_Whh[(size_t)3 * 2048 * 512];
__device__ __nv_bfloat16 g_W2 [(size_t)3 * 1536 * 512];
__device__ __nv_bfloat16 g_W3 [(size_t)3 * 1536 * 512];
__device__ __nv_bfloat16 g_W4 [(size_t)3 * 1536 * 512];
__device__ __nv_bfloat16 g_Wo [(size_t)3 * 512 * 512];
__device__ __nv_bfloat16 g_Hs [(size_t)3 * 4096 * 512];
__device__ float g_G [(size_t)8192 * 2048];
__device__ float g_c1[(size_t)4096 * 512];
__device__ float g_bias[2048 + 3 * 1536];      // b1sum | b2p | b3p | b4p

// ---- PTX helpers ------------------------------------------------------------
__device__ __forceinline__ uint32_t smem_u32(const void* p) {
    uint32_t a;
    asm("{ .reg .u64 t; cvta.to.shared.u64 t, %1; cvt.u32.u64 %0, t; }"
        : "=r"(a) : "l"(p));
    return a;
}
__device__ __forceinline__ void cp16(uint32_t dst, const void* src) {
    asm volatile("cp.async.cg.shared.global [%0], [%1], 16;"
                 :: "r"(dst), "l"(src));
}
#define CP_COMMIT() asm volatile("cp.async.commit_group;" ::: "memory")
#define CP_WAIT1()  asm volatile("cp.async.wait_group 1;" ::: "memory")

__device__ __forceinline__ void ldsm_x4(uint32_t& r0, uint32_t& r1,
                                        uint32_t& r2, uint32_t& r3,
                                        uint32_t addr) {
    asm volatile("ldmatrix.sync.aligned.m8n8.x4.shared.b16 {%0,%1,%2,%3}, [%4];"
                 : "=r"(r0), "=r"(r1), "=r"(r2), "=r"(r3) : "r"(addr));
}
__device__ __forceinline__ void mma16816(float* d, const uint32_t* a,
                                         const uint32_t* b) {
    asm volatile("mma.sync.aligned.m16n8k16.row.col.f32.bf16.bf16.f32 "
                 "{%0,%1,%2,%3}, {%4,%5,%6,%7}, {%8,%9}, {%0,%1,%2,%3};"
                 : "+f"(d[0]), "+f"(d[1]), "+f"(d[2]), "+f"(d[3])
                 : "r"(a[0]), "r"(a[1]), "r"(a[2]), "r"(a[3]),
                   "r"(b[0]), "r"(b[1]));
}
__device__ __forceinline__ uint32_t swz(uint32_t off) {
    return off ^ ((off >> 3) & 0x70);
}

// ---- splitting ----------------------------------------------------------------
__device__ __forceinline__ void split3(float a, __nv_bfloat16& o0,
                                       __nv_bfloat16& o1, __nv_bfloat16& o2) {
    __nv_bfloat16 b0 = __float2bfloat16_rn(a);
    float r = a - __bfloat162float(b0);
    __nv_bfloat16 b1 = __float2bfloat16_rn(r);
    float r2 = r - __bfloat162float(b1);
    o0 = b0; o1 = b1; o2 = __float2bfloat16_rn(r2);
}

union Pack8 { __nv_bfloat162 h[4]; uint4 v; };

__device__ __forceinline__ void split8_store(const float* v,
                                             __nv_bfloat16* P, size_t S,
                                             size_t idx8) {
    Pack8 p0, p1, p2;
#pragma unroll
    for (int k = 0; k < 4; k++) {
        __nv_bfloat16 a0, a1, a2, b0, b1, b2;
        split3(v[2 * k], a0, a1, a2);
        split3(v[2 * k + 1], b0, b1, b2);
        p0.h[k].x = a0; p0.h[k].y = b0;
        p1.h[k].x = a1; p1.h[k].y = b1;
        p2.h[k].x = a2; p2.h[k].y = b2;
    }
    ((uint4*)P)[idx8] = p0.v;
    ((uint4*)(P + S))[idx8] = p1.v;
    ((uint4*)(P + 2 * S))[idx8] = p2.v;
}

// X = concat(state[:,t], goal[:,t]) for t in {0,1}, 8 elems/thread
__global__ void split_x_kernel(const float* __restrict__ state,
                               const float* __restrict__ goal,
                               __nv_bfloat16* __restrict__ P, size_t S)
{
    size_t idx8 = (size_t)blockIdx.x * 256 + threadIdx.x;
    if (idx8 >= (size_t)8192 * INDIM / 8) return;
    size_t e = idx8 * 8;
    int row = (int)(e / INDIM);
    int col = (int)(e % INDIM);
    int b = row & 4095, t = row >> 12;
    const float* src = (col < 2048)
        ? state + (size_t)(b * 4 + t) * 2048 + col
        : goal  + (size_t)(b * 4 + t) * 1024 + (col - 2048);
    float v[8];
    *(float4*)v = *(const float4*)src;
    *(float4*)(v + 4) = *(const float4*)(src + 4);
    split8_store(v, P, S, idx8);
}

// plain weight split, 8 elems/thread
__global__ void split_w_kernel(const float* __restrict__ src,
                               __nv_bfloat16* __restrict__ P, size_t S, size_t n8)
{
    size_t idx8 = (size_t)blockIdx.x * 256 + threadIdx.x;
    if (idx8 >= n8) return;
    float v[8];
    *(float4*)v = *(const float4*)(src + idx8 * 8);
    *(float4*)(v + 4) = *(const float4*)(src + idx8 * 8 + 4);
    split8_store(v, P, S, idx8);
}

// pruned weight split: out rows [i|g|o] (1536), src rows [i|f|g|o] (2048), K=512
__global__ void split_w_prune_kernel(const float* __restrict__ src,
                                     __nv_bfloat16* __restrict__ P, size_t S)
{
    size_t idx8 = (size_t)blockIdx.x * 256 + threadIdx.x;
    if (idx8 >= (size_t)NPRU * 512 / 8) return;
    size_t e = idx8 * 8;
    int row = (int)(e >> 9);
    int col = (int)(e & 511);
    int srow = (row < 512) ? row : row + 512;
    const float* s = src + (size_t)srow * 512 + col;
    float v[8];
    *(float4*)v = *(const float4*)s;
    *(float4*)(v + 4) = *(const float4*)(s + 4);
    split8_store(v, P, S, idx8);
}

// bias pre-pack: b1sum(2048) then pruned b2/b3/b4 sums (1536 each)
__global__ void bias_pack_kernel(const float* bih1, const float* bhh1,
                                 const float* bih2, const float* bhh2,
                                 const float* bih3, const float* bhh3,
                                 const float* bih4, const float* bhh4,
                                 float* __restrict__ out)
{
    int i = blockIdx.x * 256 + threadIdx.x;
    if (i < 2048) { out[i] = bih1[i] + bhh1[i]; return; }
    int j = i - 2048;
    if (j >= 3 * NPRU) return;
    int layer = j / NPRU;
    int n = j - layer * NPRU;
    int sn = (n < 512) ? n : n + 512;
    const float* bi = (layer == 0) ? bih2 : (layer == 1) ? bih3 : bih4;
    const float* bh = (layer == 0) ? bhh2 : (layer == 1) ? bhh3 : bhh4;
    out[i] = bi[sn] + bh[sn];
}

// ---- LSTM cell epilogues (vectorized x4) -------------------------------------
__device__ __forceinline__ float sigm(float x) { return 1.0f / (1.0f + expf(-x)); }

union Pack4 { __nv_bfloat162 h[2]; uint2 v; };

__device__ __forceinline__ void split4_store(const float* v,
                                             __nv_bfloat16* HP, size_t S,
                                             size_t idx4) {
    Pack4 p0, p1, p2;
#pragma unroll
    for (int k = 0; k < 2; k++) {
        __nv_bfloat16 a0, a1, a2, b0, b1, b2;
        split3(v[2 * k], a0, a1, a2);
        split3(v[2 * k + 1], b0, b1, b2);
        p0.h[k].x = a0; p0.h[k].y = b0;
        p1.h[k].x = a1; p1.h[k].y = b1;
        p2.h[k].x = a2; p2.h[k].y = b2;
    }
    ((uint2*)HP)[idx4] = p0.v;
    ((uint2*)(HP + S))[idx4] = p1.v;
    ((uint2*)(HP + 2 * S))[idx4] = p2.v;
}

// c_prev = 0 cell; gate row layout parametrized (gstride, g at +goff, o at +ooff)
__global__ void cell_zero_kernel(const float* __restrict__ gates,
                                 int gstride, int goff, int ooff,
                                 __nv_bfloat16* __restrict__ HP, size_t S,
                                 float* __restrict__ c)
{
    int idx4 = blockIdx.x * 256 + threadIdx.x;
    if (idx4 >= BATCH * HID / 4) return;
    int m = idx4 >> 7;
    int n = (idx4 & 127) << 2;
    const float* gr = gates + (size_t)m * gstride + n;
    float4 gi = *(const float4*)(gr);
    float4 gg = *(const float4*)(gr + goff);
    float4 go = *(const float4*)(gr + ooff);
    float hv[4], cv[4];
    const float* gip = &gi.x; const float* ggp = &gg.x; const float* gop = &go.x;
#pragma unroll
    for (int k = 0; k < 4; k++) {
        float cn = sigm(gip[k]) * tanhf(ggp[k]);
        hv[k] = fmaxf(sigm(gop[k]) * tanhf(cn), 0.f);
        cv[k] = fmaxf(cn, 0.f);
    }
    split4_store(hv, HP, S, idx4);
    if (c) *(float4*)(c + (size_t)idx4 * 4) = make_float4(cv[0], cv[1], cv[2], cv[3]);
}

// full step (layout fixed 2048: f at +512, g at +1024, o at +1536)
__global__ void cell_step_kernel(const float* __restrict__ gates,
                                 const float* __restrict__ cprev,
                                 __nv_bfloat16* __restrict__ HP, size_t S)
{
    int idx4 = blockIdx.x * 256 + threadIdx.x;
    if (idx4 >= BATCH * HID / 4) return;
    int m = idx4 >> 7;
    int n = (idx4 & 127) << 2;
    const float* gr = gates + (size_t)m * G4 + n;
    float4 gi = *(const float4*)(gr);
    float4 gf = *(const float4*)(gr + 512);
    float4 gg = *(const float4*)(gr + 1024);
    float4 go = *(const float4*)(gr + 1536);
    float4 cp = *(const float4*)(cprev + (size_t)idx4 * 4);
    float hv[4];
    const float* gip = &gi.x; const float* gfp = &gf.x;
    const float* ggp = &gg.x; const float* gop = &go.x;
    const float* cpp = &cp.x;
#pragma unroll
    for (int k = 0; k < 4; k++) {
        float cn = sigm(gfp[k]) * cpp[k] + sigm(gip[k]) * tanhf(ggp[k]);
        hv[k] = fmaxf(sigm(gop[k]) * tanhf(cn), 0.f);
    }
    split4_store(hv, HP, S, idx4);
}

// ===========================================================================
// HMMA GEMM (same core as R4, single sync per chunk, single bias vector)
// ===========================================================================
#define STAGE_BYTES 32768
#define NSTAGE 3
#define GSMEM  (NSTAGE * STAGE_BYTES)

__global__ void __launch_bounds__(256, 2)
mma_gemm(const __nv_bfloat16* __restrict__ Ap, size_t aPlane,
         const __nv_bfloat16* __restrict__ Bp, size_t bPlane,
         float* __restrict__ C,
         const float* __restrict__ bias,
         const float* __restrict__ U, float* __restrict__ Out,
         int M, int N, int K, int mode)
{
    extern __shared__ __align__(1024) char smem[];
    const uint32_t smb = smem_u32(smem);
    const int tid  = threadIdx.x;
    const int lane = tid & 31;
    const int wid  = tid >> 5;
    const int wm   = wid & 3;
    const int wn   = wid >> 2;
    const int bm   = blockIdx.y * 128;
    const int bn   = blockIdx.x * 128;

    const int PA[6] = {2, 0, 1, 1, 0, 0};
    const int PB[6] = {0, 2, 1, 0, 1, 0};

    const __nv_bfloat16* Ab[6];
    const __nv_bfloat16* Bb[6];
#pragma unroll
    for (int p = 0; p < 6; p++) {
        Ab[p] = Ap + (size_t)PA[p] * aPlane + (size_t)bm * K;
        Bb[p] = Bp + (size_t)PB[p] * bPlane + (size_t)bn * K;
    }

    const int kper = K >> 6;
    const int NCH  = 6 * kper;

    const int lrow = tid >> 3;
    const int lcu  = tid & 7;
    auto issue = [&](int c) {
        if (c < NCH) {
            int pr = c / kper;
            int kc = c - pr * kper;
            const __nv_bfloat16* As = Ab[pr] + kc * 64;
            const __nv_bfloat16* Bs = Bb[pr] + kc * 64;
            uint32_t sb = smb + (c % NSTAGE) * STAGE_BYTES;
#pragma unroll
            for (int i = 0; i < 4; i++) {
                int row = lrow + i * 32;
                uint32_t off = swz((uint32_t)(row * 128 + lcu * 16));
                cp16(sb + off, As + (size_t)row * K + lcu * 8);
                cp16(sb + 16384 + off, Bs + (size_t)row * K + lcu * 8);
            }
        }
        CP_COMMIT();
    };

    float acc[2][8][4];
#pragma unroll
    for (int i = 0; i < 2; i++)
#pragma unroll
        for (int j = 0; j < 8; j++)
#pragma unroll
            for (int v = 0; v < 4; v++) acc[i][j][v] = 0.f;

    issue(0);
    issue(1);

    const int a_row = wm * 32 + (lane & 7) + ((lane >> 3) & 1) * 8;
    const int a_kb  = ((lane >> 4) & 1) * 16;
    const int b_row = wn * 64 + (lane & 7) + ((lane >> 4) & 1) * 8;
    const int b_kb  = ((lane >> 3) & 1) * 16;

    for (int c = 0; c < NCH; c++) {
        CP_WAIT1();
        __syncthreads();
        issue(c + 2);

        uint32_t sA = smb + (c % NSTAGE) * STAGE_BYTES;
        uint32_t sB = sA + 16384;

#pragma unroll
        for (int ks = 0; ks < 4; ks++) {
            uint32_t a[2][4];
#pragma unroll
            for (int i = 0; i < 2; i++) {
                uint32_t off = swz((uint32_t)((a_row + i * 16) * 128 + ks * 32 + a_kb));
                ldsm_x4(a[i][0], a[i][1], a[i][2], a[i][3], sA + off);
            }
            uint32_t b[8][2];
#pragma unroll
            for (int j2 = 0; j2 < 4; j2++) {
                uint32_t off = swz((uint32_t)((b_row + j2 * 16) * 128 + ks * 32 + b_kb));
                ldsm_x4(b[2 * j2][0], b[2 * j2][1], b[2 * j2 + 1][0],
                        b[2 * j2 + 1][1], sB + off);
            }
#pragma unroll
            for (int i = 0; i < 2; i++)
#pragma unroll
                for (int j = 0; j < 8; j++)
                    mma16816(acc[i][j], a[i], b[j]);
        }
    }

    // ---- epilogue ----
    const int r0    = bm + wm * 32 + (lane >> 2);
    const int cbase = bn + wn * 64 + (lane & 3) * 2;

#pragma unroll
    for (int i = 0; i < 2; i++) {
        const int rowA = r0 + i * 16;
#pragma unroll
        for (int j = 0; j < 8; j++) {
            const int col = cbase + j * 8;
            float v0 = acc[i][j][0], v1 = acc[i][j][1];
            float v2 = acc[i][j][2], v3 = acc[i][j][3];
            if (mode == 0) {
                float b0 = bias[col], b1 = bias[col + 1];
                *(float2*)(C + (size_t)rowA * N + col)       = make_float2(v0 + b0, v1 + b1);
                *(float2*)(C + (size_t)(rowA + 8) * N + col) = make_float2(v2 + b0, v3 + b1);
            } else if (mode == 1) {
                float2* p0 = (float2*)(C + (size_t)rowA * N + col);
                float2* p1 = (float2*)(C + (size_t)(rowA + 8) * N + col);
                float2 o0 = *p0, o1 = *p1;
                *p0 = make_float2(o0.x + v0, o0.y + v1);
                *p1 = make_float2(o1.x + v2, o1.y + v3);
            } else {
                float b0 = bias[col], b1 = bias[col + 1];
                const float2 u0 = *(const float2*)(U + (size_t)rowA * N + col);
                const float2 u1 = *(const float2*)(U + (size_t)(rowA + 8) * N + col);
                float p00 = fmaxf(v0 + b0, 0.f), p01 = fmaxf(v1 + b1, 0.f);
                float p10 = fmaxf(v2 + b0, 0.f), p11 = fmaxf(v3 + b1, 0.f);
                *(float2*)(Out + (size_t)rowA * N + col) =
                    make_float2(u0.x < p00 ? 1.f : 0.f, u0.y < p01 ? 1.f : 0.f);
                *(float2*)(Out + (size_t)(rowA + 8) * N + col) =
                    make_float2(u1.x < p10 ? 1.f : 0.f, u1.y < p11 ? 1.f : 0.f);
            }
        }
    }
}

// ===========================================================================
extern "C" void kernel_launch(void* const* d_in, const int* in_sizes, int n_in,
                              void* d_out, int out_size)
{
    const float* state = (const float*)d_in[0];
    const float* goal  = (const float*)d_in[1];
    const float* u     = (const float*)d_in[2];
    const float* Wih1  = (const float*)d_in[3];
    const float* Whh1  = (const float*)d_in[4];
    const float* bih1  = (const float*)d_in[5];
    const float* bhh1  = (const float*)d_in[6];
    const float* Wih2  = (const float*)d_in[7];
    const float* bih2  = (const float*)d_in[9];
    const float* bhh2  = (const float*)d_in[10];
    const float* Wih3  = (const float*)d_in[11];
    const float* bih3  = (const float*)d_in[13];
    const float* bhh3  = (const float*)d_in[14];
    const float* Wih4  = (const float*)d_in[15];
    const float* bih4  = (const float*)d_in[17];
    const float* bhh4  = (const float*)d_in[18];
    const float* Wout  = (const float*)d_in[19];
    const float* bout  = (const float*)d_in[20];
    float* out = (float*)d_out;

    __nv_bfloat16 *XA, *W1, *Whh, *W2, *W3, *W4, *Wo, *Hs;
    float *G, *c1, *bias;
    cudaGetSymbolAddress((void**)&XA,  g_XA);
    cudaGetSymbolAddress((void**)&W1,  g_W1);
    cudaGetSymbolAddress((void**)&Whh, g_Whh);
    cudaGetSymbolAddress((void**)&W2,  g_W2);
    cudaGetSymbolAddress((void**)&W3,  g_W3);
    cudaGetSymbolAddress((void**)&W4,  g_W4);
    cudaGetSymbolAddress((void**)&Wo,  g_Wo);
    cudaGetSymbolAddress((void**)&Hs,  g_Hs);
    cudaGetSymbolAddress((void**)&G,   g_G);
    cudaGetSymbolAddress((void**)&c1,  g_c1);
    cudaGetSymbolAddress((void**)&bias, g_bias);

    cudaFuncSetAttribute(mma_gemm, cudaFuncAttributeMaxDynamicSharedMemorySize,
                         GSMEM);

    const size_t SX  = (size_t)8192 * 3072;
    const size_t SW1 = (size_t)2048 * 3072;
    const size_t SWs = (size_t)2048 * 512;
    const size_t SWp = (size_t)NPRU * 512;
    const size_t SWo = (size_t)512 * 512;
    const size_t SH  = (size_t)4096 * 512;
    float* G1 = G + (size_t)4096 * 2048;
    float* b1s = bias;
    float* b2p = bias + 2048;
    float* b3p = b2p + NPRU;
    float* b4p = b3p + NPRU;

    // ---- splits (8 elems per thread) ----
    split_x_kernel<<<(int)(SX / 8 / 256), 256>>>(state, goal, XA, SX);
    split_w_kernel<<<(int)(SW1 / 8 / 256), 256>>>(Wih1, W1, SW1, SW1 / 8);
    split_w_kernel<<<(int)(SWs / 8 / 256), 256>>>(Whh1, Whh, SWs, SWs / 8);
    split_w_prune_kernel<<<(int)(SWp / 8 / 256), 256>>>(Wih2, W2, SWp);
    split_w_prune_kernel<<<(int)(SWp / 8 / 256), 256>>>(Wih3, W3, SWp);
    split_w_prune_kernel<<<(int)(SWp / 8 / 256), 256>>>(Wih4, W4, SWp);
    split_w_kernel<<<(int)(SWo / 8 / 256), 256>>>(Wout, Wo, SWo, SWo / 8);
    bias_pack_kernel<<<(2048 + 3 * NPRU + 255) / 256, 256>>>(
        bih1, bhh1, bih2, bhh2, bih3, bhh3, bih4, bhh4, bias);

    // ---- big GEMM: G = X @ Wih1^T + b1sum ----
    mma_gemm<<<dim3(2048 / 128, 8192 / 128), 256, GSMEM>>>(
        XA, SX, W1, SW1, G, b1s, nullptr, nullptr, 8192, 2048, 3072, 0);

    cell_zero_kernel<<<BATCH * HID / 4 / 256, 256>>>(G, 2048, 1024, 1536, Hs, SH, c1);

    mma_gemm<<<dim3(2048 / 128, 4096 / 128), 256, GSMEM>>>(
        Hs, SH, Whh, SWs, G1, nullptr, nullptr, nullptr, 4096, 2048, 512, 1);

    cell_step_kernel<<<BATCH * HID / 4 / 256, 256>>>(G1, c1, Hs, SH);

    // pruned layers (N=1536, gate layout [i|g|o])
    mma_gemm<<<dim3(NPRU / 128, 4096 / 128), 256, GSMEM>>>(
        Hs, SH, W2, SWp, G, b2p, nullptr, nullptr, 4096, NPRU, 512, 0);
    cell_zero_kernel<<<BATCH * HID / 4 / 256, 256>>>(G, NPRU, 512, 1024, Hs, SH, nullptr);

    mma_gemm<<<dim3(NPRU / 128, 4096 / 128), 256, GSMEM>>>(
        Hs, SH, W3, SWp, G, b3p, nullptr, nullptr, 4096, NPRU, 512, 0);
    cell_zero_kernel<<<BATCH * HID / 4 / 256, 256>>>(G, NPRU, 512, 1024, Hs, SH, nullptr);

    mma_gemm<<<dim3(NPRU / 128, 4096 / 128), 256, GSMEM>>>(
        Hs, SH, W4, SWp, G, b4p, nullptr, nullptr, 4096, NPRU, 512, 0);
    cell_zero_kernel<<<BATCH * HID / 4 / 256, 256>>>(G, NPRU, 512, 1024, Hs, SH, nullptr);

    // head: out = (u < relu(h4 @ Wout^T + bout))
    mma_gemm<<<dim3(512 / 128, 4096 / 128), 256, GSMEM>>>(
        Hs, SH, Wo, SWo, nullptr, bout, u, out, 4096, 512, 512, 2);
}

// round 6
// speedup vs baseline: 3.3483x; 1.8815x over previous
#include <cuda_runtime.h>
#include <cuda_fp16.h>
#include <math.h>
#include <stdint.h>

// ===========================================================================
// Actor_10505490006716 — HMMA (mma.sync fp16) with 2-plane fp32 split.
// Round 6: fp16 split (11-bit mantissa) -> 2 planes, 3 products (00,01,10);
// dropped a1*b1 term is <= 2^-24 relative (same scale as fp32 roundoff).
// Halves tensor-core FLOPs vs the bf16 3-plane / 6-product scheme.
// Keeps: f-gate pruning in layers 2-4 (N=1536), fused biases, vectorized
// split/cell kernels, 3-stage cp.async pipeline, single-sync mainloop.
// ===========================================================================

#define BATCH 4096
#define HID   512
#define G4    2048
#define INDIM 3072
#define NPRU  1536

__device__ __half g_XA [(size_t)2 * 8192 * 3072];
__device__ __half g_W1 [(size_t)2 * 2048 * 3072];
__device__ __half g_Whh[(size_t)2 * 2048 * 512];
__device__ __half g_W2 [(size_t)2 * 1536 * 512];
__device__ __half g_W3 [(size_t)2 * 1536 * 512];
__device__ __half g_W4 [(size_t)2 * 1536 * 512];
__device__ __half g_Wo [(size_t)2 * 512 * 512];
__device__ __half g_Hs [(size_t)2 * 4096 * 512];
__device__ float g_G [(size_t)8192 * 2048];
__device__ float g_c1[(size_t)4096 * 512];
__device__ float g_bias[2048 + 3 * 1536];      // b1sum | b2p | b3p | b4p

// ---- PTX helpers ------------------------------------------------------------
__device__ __forceinline__ uint32_t smem_u32(const void* p) {
    uint32_t a;
    asm("{ .reg .u64 t; cvta.to.shared.u64 t, %1; cvt.u32.u64 %0, t; }"
        : "=r"(a) : "l"(p));
    return a;
}
__device__ __forceinline__ void cp16(uint32_t dst, const void* src) {
    asm volatile("cp.async.cg.shared.global [%0], [%1], 16;"
                 :: "r"(dst), "l"(src));
}
#define CP_COMMIT() asm volatile("cp.async.commit_group;" ::: "memory")
#define CP_WAIT1()  asm volatile("cp.async.wait_group 1;" ::: "memory")

__device__ __forceinline__ void ldsm_x4(uint32_t& r0, uint32_t& r1,
                                        uint32_t& r2, uint32_t& r3,
                                        uint32_t addr) {
    asm volatile("ldmatrix.sync.aligned.m8n8.x4.shared.b16 {%0,%1,%2,%3}, [%4];"
                 : "=r"(r0), "=r"(r1), "=r"(r2), "=r"(r3) : "r"(addr));
}
__device__ __forceinline__ void mma16816(float* d, const uint32_t* a,
                                         const uint32_t* b) {
    asm volatile("mma.sync.aligned.m16n8k16.row.col.f32.f16.f16.f32 "
                 "{%0,%1,%2,%3}, {%4,%5,%6,%7}, {%8,%9}, {%0,%1,%2,%3};"
                 : "+f"(d[0]), "+f"(d[1]), "+f"(d[2]), "+f"(d[3])
                 : "r"(a[0]), "r"(a[1]), "r"(a[2]), "r"(a[3]),
                   "r"(b[0]), "r"(b[1]));
}
__device__ __forceinline__ uint32_t swz(uint32_t off) {
    return off ^ ((off >> 3) & 0x70);
}

// ---- fp16 2-plane splitting ---------------------------------------------------
__device__ __forceinline__ void split2(float a, __half& o0, __half& o1) {
    __half b0 = __float2half_rn(a);
    o0 = b0;
    o1 = __float2half_rn(a - __half2float(b0));
}

union Pack8 { __half2 h[4]; uint4 v; };

__device__ __forceinline__ void split8_store(const float* v,
                                             __half* P, size_t S,
                                             size_t idx8) {
    Pack8 p0, p1;
#pragma unroll
    for (int k = 0; k < 4; k++) {
        __half a0, a1, b0, b1;
        split2(v[2 * k], a0, a1);
        split2(v[2 * k + 1], b0, b1);
        p0.h[k].x = a0; p0.h[k].y = b0;
        p1.h[k].x = a1; p1.h[k].y = b1;
    }
    ((uint4*)P)[idx8] = p0.v;
    ((uint4*)(P + S))[idx8] = p1.v;
}

// X = concat(state[:,t], goal[:,t]) for t in {0,1}, 8 elems/thread
__global__ void split_x_kernel(const float* __restrict__ state,
                               const float* __restrict__ goal,
                               __half* __restrict__ P, size_t S)
{
    size_t idx8 = (size_t)blockIdx.x * 256 + threadIdx.x;
    if (idx8 >= (size_t)8192 * INDIM / 8) return;
    size_t e = idx8 * 8;
    int row = (int)(e / INDIM);
    int col = (int)(e % INDIM);
    int b = row & 4095, t = row >> 12;
    const float* src = (col < 2048)
        ? state + (size_t)(b * 4 + t) * 2048 + col
        : goal  + (size_t)(b * 4 + t) * 1024 + (col - 2048);
    float v[8];
    *(float4*)v = *(const float4*)src;
    *(float4*)(v + 4) = *(const float4*)(src + 4);
    split8_store(v, P, S, idx8);
}

__global__ void split_w_kernel(const float* __restrict__ src,
                               __half* __restrict__ P, size_t S, size_t n8)
{
    size_t idx8 = (size_t)blockIdx.x * 256 + threadIdx.x;
    if (idx8 >= n8) return;
    float v[8];
    *(float4*)v = *(const float4*)(src + idx8 * 8);
    *(float4*)(v + 4) = *(const float4*)(src + idx8 * 8 + 4);
    split8_store(v, P, S, idx8);
}

// pruned weight split: out rows [i|g|o] (1536), src rows [i|f|g|o] (2048), K=512
__global__ void split_w_prune_kernel(const float* __restrict__ src,
                                     __half* __restrict__ P, size_t S)
{
    size_t idx8 = (size_t)blockIdx.x * 256 + threadIdx.x;
    if (idx8 >= (size_t)NPRU * 512 / 8) return;
    size_t e = idx8 * 8;
    int row = (int)(e >> 9);
    int col = (int)(e & 511);
    int srow = (row < 512) ? row : row + 512;
    const float* s = src + (size_t)srow * 512 + col;
    float v[8];
    *(float4*)v = *(const float4*)s;
    *(float4*)(v + 4) = *(const float4*)(s + 4);
    split8_store(v, P, S, idx8);
}

__global__ void bias_pack_kernel(const float* bih1, const float* bhh1,
                                 const float* bih2, const float* bhh2,
                                 const float* bih3, const float* bhh3,
                                 const float* bih4, const float* bhh4,
                                 float* __restrict__ out)
{
    int i = blockIdx.x * 256 + threadIdx.x;
    if (i < 2048) { out[i] = bih1[i] + bhh1[i]; return; }
    int j = i - 2048;
    if (j >= 3 * NPRU) return;
    int layer = j / NPRU;
    int n = j - layer * NPRU;
    int sn = (n < 512) ? n : n + 512;
    const float* bi = (layer == 0) ? bih2 : (layer == 1) ? bih3 : bih4;
    const float* bh = (layer == 0) ? bhh2 : (layer == 1) ? bhh3 : bhh4;
    out[i] = bi[sn] + bh[sn];
}

// ---- LSTM cell epilogues (vectorized x4, write 2 fp16 planes) ------------------
__device__ __forceinline__ float sigm(float x) { return 1.0f / (1.0f + expf(-x)); }

union Pack4 { __half2 h[2]; uint2 v; };

__device__ __forceinline__ void split4_store(const float* v,
                                             __half* HP, size_t S,
                                             size_t idx4) {
    Pack4 p0, p1;
#pragma unroll
    for (int k = 0; k < 2; k++) {
        __half a0, a1, b0, b1;
        split2(v[2 * k], a0, a1);
        split2(v[2 * k + 1], b0, b1);
        p0.h[k].x = a0; p0.h[k].y = b0;
        p1.h[k].x = a1; p1.h[k].y = b1;
    }
    ((uint2*)HP)[idx4] = p0.v;
    ((uint2*)(HP + S))[idx4] = p1.v;
}

__global__ void cell_zero_kernel(const float* __restrict__ gates,
                                 int gstride, int goff, int ooff,
                                 __half* __restrict__ HP, size_t S,
                                 float* __restrict__ c)
{
    int idx4 = blockIdx.x * 256 + threadIdx.x;
    if (idx4 >= BATCH * HID / 4) return;
    int m = idx4 >> 7;
    int n = (idx4 & 127) << 2;
    const float* gr = gates + (size_t)m * gstride + n;
    float4 gi = *(const float4*)(gr);
    float4 gg = *(const float4*)(gr + goff);
    float4 go = *(const float4*)(gr + ooff);
    float hv[4], cv[4];
    const float* gip = &gi.x; const float* ggp = &gg.x; const float* gop = &go.x;
#pragma unroll
    for (int k = 0; k < 4; k++) {
        float cn = sigm(gip[k]) * tanhf(ggp[k]);
        hv[k] = fmaxf(sigm(gop[k]) * tanhf(cn), 0.f);
        cv[k] = fmaxf(cn, 0.f);
    }
    split4_store(hv, HP, S, idx4);
    if (c) *(float4*)(c + (size_t)idx4 * 4) = make_float4(cv[0], cv[1], cv[2], cv[3]);
}

__global__ void cell_step_kernel(const float* __restrict__ gates,
                                 const float* __restrict__ cprev,
                                 __half* __restrict__ HP, size_t S)
{
    int idx4 = blockIdx.x * 256 + threadIdx.x;
    if (idx4 >= BATCH * HID / 4) return;
    int m = idx4 >> 7;
    int n = (idx4 & 127) << 2;
    const float* gr = gates + (size_t)m * G4 + n;
    float4 gi = *(const float4*)(gr);
    float4 gf = *(const float4*)(gr + 512);
    float4 gg = *(const float4*)(gr + 1024);
    float4 go = *(const float4*)(gr + 1536);
    float4 cp = *(const float4*)(cprev + (size_t)idx4 * 4);
    float hv[4];
    const float* gip = &gi.x; const float* gfp = &gf.x;
    const float* ggp = &gg.x; const float* gop = &go.x;
    const float* cpp = &cp.x;
#pragma unroll
    for (int k = 0; k < 4; k++) {
        float cn = sigm(gfp[k]) * cpp[k] + sigm(gip[k]) * tanhf(ggp[k]);
        hv[k] = fmaxf(sigm(gop[k]) * tanhf(cn), 0.f);
    }
    split4_store(hv, HP, S, idx4);
}

// ===========================================================================
// HMMA GEMM: C = sum over 3 plane products (01, 10, 00) of Ai * Bj^T
// CTA tile 128x128, K-chunk 64 fp16 (128B rows), 3-stage cp.async pipeline.
//   mode 0: C = acc + bias[n]; mode 1: C += acc;
//   mode 2: Out = (U < relu(acc + bias[n])) ? 1 : 0
// ===========================================================================
#define STAGE_BYTES 32768
#define NSTAGE 3
#define GSMEM  (NSTAGE * STAGE_BYTES)

__global__ void __launch_bounds__(256, 2)
mma_gemm(const __half* __restrict__ Ap, size_t aPlane,
         const __half* __restrict__ Bp, size_t bPlane,
         float* __restrict__ C,
         const float* __restrict__ bias,
         const float* __restrict__ U, float* __restrict__ Out,
         int M, int N, int K, int mode)
{
    extern __shared__ __align__(1024) char smem[];
    const uint32_t smb = smem_u32(smem);
    const int tid  = threadIdx.x;
    const int lane = tid & 31;
    const int wid  = tid >> 5;
    const int wm   = wid & 3;
    const int wn   = wid >> 2;
    const int bm   = blockIdx.y * 128;
    const int bn   = blockIdx.x * 128;

    // products smallest-first: a0*b1, a1*b0, a0*b0
    const int PA[3] = {0, 1, 0};
    const int PB[3] = {1, 0, 0};

    const __half* Ab[3];
    const __half* Bb[3];
#pragma unroll
    for (int p = 0; p < 3; p++) {
        Ab[p] = Ap + (size_t)PA[p] * aPlane + (size_t)bm * K;
        Bb[p] = Bp + (size_t)PB[p] * bPlane + (size_t)bn * K;
    }

    const int kper = K >> 6;
    const int NCH  = 3 * kper;

    const int lrow = tid >> 3;
    const int lcu  = tid & 7;
    auto issue = [&](int c) {
        if (c < NCH) {
            int pr = c / kper;
            int kc = c - pr * kper;
            const __half* As = Ab[pr] + kc * 64;
            const __half* Bs = Bb[pr] + kc * 64;
            uint32_t sb = smb + (c % NSTAGE) * STAGE_BYTES;
#pragma unroll
            for (int i = 0; i < 4; i++) {
                int row = lrow + i * 32;
                uint32_t off = swz((uint32_t)(row * 128 + lcu * 16));
                cp16(sb + off, As + (size_t)row * K + lcu * 8);
                cp16(sb + 16384 + off, Bs + (size_t)row * K + lcu * 8);
            }
        }
        CP_COMMIT();
    };

    float acc[2][8][4];
#pragma unroll
    for (int i = 0; i < 2; i++)
#pragma unroll
        for (int j = 0; j < 8; j++)
#pragma unroll
            for (int v = 0; v < 4; v++) acc[i][j][v] = 0.f;

    issue(0);
    issue(1);

    const int a_row = wm * 32 + (lane & 7) + ((lane >> 3) & 1) * 8;
    const int a_kb  = ((lane >> 4) & 1) * 16;
    const int b_row = wn * 64 + (lane & 7) + ((lane >> 4) & 1) * 8;
    const int b_kb  = ((lane >> 3) & 1) * 16;

    for (int c = 0; c < NCH; c++) {
        CP_WAIT1();
        __syncthreads();
        issue(c + 2);

        uint32_t sA = smb + (c % NSTAGE) * STAGE_BYTES;
        uint32_t sB = sA + 16384;

#pragma unroll
        for (int ks = 0; ks < 4; ks++) {
            uint32_t a[2][4];
#pragma unroll
            for (int i = 0; i < 2; i++) {
                uint32_t off = swz((uint32_t)((a_row + i * 16) * 128 + ks * 32 + a_kb));
                ldsm_x4(a[i][0], a[i][1], a[i][2], a[i][3], sA + off);
            }
            uint32_t b[8][2];
#pragma unroll
            for (int j2 = 0; j2 < 4; j2++) {
                uint32_t off = swz((uint32_t)((b_row + j2 * 16) * 128 + ks * 32 + b_kb));
                ldsm_x4(b[2 * j2][0], b[2 * j2][1], b[2 * j2 + 1][0],
                        b[2 * j2 + 1][1], sB + off);
            }
#pragma unroll
            for (int i = 0; i < 2; i++)
#pragma unroll
                for (int j = 0; j < 8; j++)
                    mma16816(acc[i][j], a[i], b[j]);
        }
    }

    // ---- epilogue ----
    const int r0    = bm + wm * 32 + (lane >> 2);
    const int cbase = bn + wn * 64 + (lane & 3) * 2;

#pragma unroll
    for (int i = 0; i < 2; i++) {
        const int rowA = r0 + i * 16;
#pragma unroll
        for (int j = 0; j < 8; j++) {
            const int col = cbase + j * 8;
            float v0 = acc[i][j][0], v1 = acc[i][j][1];
            float v2 = acc[i][j][2], v3 = acc[i][j][3];
            if (mode == 0) {
                float b0 = bias[col], b1 = bias[col + 1];
                *(float2*)(C + (size_t)rowA * N + col)       = make_float2(v0 + b0, v1 + b1);
                *(float2*)(C + (size_t)(rowA + 8) * N + col) = make_float2(v2 + b0, v3 + b1);
            } else if (mode == 1) {
                float2* p0 = (float2*)(C + (size_t)rowA * N + col);
                float2* p1 = (float2*)(C + (size_t)(rowA + 8) * N + col);
                float2 o0 = *p0, o1 = *p1;
                *p0 = make_float2(o0.x + v0, o0.y + v1);
                *p1 = make_float2(o1.x + v2, o1.y + v3);
            } else {
                float b0 = bias[col], b1 = bias[col + 1];
                const float2 u0 = *(const float2*)(U + (size_t)rowA * N + col);
                const float2 u1 = *(const float2*)(U + (size_t)(rowA + 8) * N + col);
                float p00 = fmaxf(v0 + b0, 0.f), p01 = fmaxf(v1 + b1, 0.f);
                float p10 = fmaxf(v2 + b0, 0.f), p11 = fmaxf(v3 + b1, 0.f);
                *(float2*)(Out + (size_t)rowA * N + col) =
                    make_float2(u0.x < p00 ? 1.f : 0.f, u0.y < p01 ? 1.f : 0.f);
                *(float2*)(Out + (size_t)(rowA + 8) * N + col) =
                    make_float2(u1.x < p10 ? 1.f : 0.f, u1.y < p11 ? 1.f : 0.f);
            }
        }
    }
}

// ===========================================================================
extern "C" void kernel_launch(void* const* d_in, const int* in_sizes, int n_in,
                              void* d_out, int out_size)
{
    const float* state = (const float*)d_in[0];
    const float* goal  = (const float*)d_in[1];
    const float* u     = (const float*)d_in[2];
    const float* Wih1  = (const float*)d_in[3];
    const float* Whh1  = (const float*)d_in[4];
    const float* bih1  = (const float*)d_in[5];
    const float* bhh1  = (const float*)d_in[6];
    const float* Wih2  = (const float*)d_in[7];
    const float* bih2  = (const float*)d_in[9];
    const float* bhh2  = (const float*)d_in[10];
    const float* Wih3  = (const float*)d_in[11];
    const float* bih3  = (const float*)d_in[13];
    const float* bhh3  = (const float*)d_in[14];
    const float* Wih4  = (const float*)d_in[15];
    const float* bih4  = (const float*)d_in[17];
    const float* bhh4  = (const float*)d_in[18];
    const float* Wout  = (const float*)d_in[19];
    const float* bout  = (const float*)d_in[20];
    float* out = (float*)d_out;

    __half *XA, *W1, *Whh, *W2, *W3, *W4, *Wo, *Hs;
    float *G, *c1, *bias;
    cudaGetSymbolAddress((void**)&XA,  g_XA);
    cudaGetSymbolAddress((void**)&W1,  g_W1);
    cudaGetSymbolAddress((void**)&Whh, g_Whh);
    cudaGetSymbolAddress((void**)&W2,  g_W2);
    cudaGetSymbolAddress((void**)&W3,  g_W3);
    cudaGetSymbolAddress((void**)&W4,  g_W4);
    cudaGetSymbolAddress((void**)&Wo,  g_Wo);
    cudaGetSymbolAddress((void**)&Hs,  g_Hs);
    cudaGetSymbolAddress((void**)&G,   g_G);
    cudaGetSymbolAddress((void**)&c1,  g_c1);
    cudaGetSymbolAddress((void**)&bias, g_bias);

    cudaFuncSetAttribute(mma_gemm, cudaFuncAttributeMaxDynamicSharedMemorySize,
                         GSMEM);

    const size_t SX  = (size_t)8192 * 3072;
    const size_t SW1 = (size_t)2048 * 3072;
    const size_t SWs = (size_t)2048 * 512;
    const size_t SWp = (size_t)NPRU * 512;
    const size_t SWo = (size_t)512 * 512;
    const size_t SH  = (size_t)4096 * 512;
    float* G1 = G + (size_t)4096 * 2048;
    float* b1s = bias;
    float* b2p = bias + 2048;
    float* b3p = b2p + NPRU;
    float* b4p = b3p + NPRU;

    // ---- splits (8 elems per thread, 2 fp16 planes) ----
    split_x_kernel<<<(int)(SX / 8 / 256), 256>>>(state, goal, XA, SX);
    split_w_kernel<<<(int)(SW1 / 8 / 256), 256>>>(Wih1, W1, SW1, SW1 / 8);
    split_w_kernel<<<(int)(SWs / 8 / 256), 256>>>(Whh1, Whh, SWs, SWs / 8);
    split_w_prune_kernel<<<(int)(SWp / 8 / 256), 256>>>(Wih2, W2, SWp);
    split_w_prune_kernel<<<(int)(SWp / 8 / 256), 256>>>(Wih3, W3, SWp);
    split_w_prune_kernel<<<(int)(SWp / 8 / 256), 256>>>(Wih4, W4, SWp);
    split_w_kernel<<<(int)(SWo / 8 / 256), 256>>>(Wout, Wo, SWo, SWo / 8);
    bias_pack_kernel<<<(2048 + 3 * NPRU + 255) / 256, 256>>>(
        bih1, bhh1, bih2, bhh2, bih3, bhh3, bih4, bhh4, bias);

    // ---- big GEMM: G = X @ Wih1^T + b1sum ----
    mma_gemm<<<dim3(2048 / 128, 8192 / 128), 256, GSMEM>>>(
        XA, SX, W1, SW1, G, b1s, nullptr, nullptr, 8192, 2048, 3072, 0);

    cell_zero_kernel<<<BATCH * HID / 4 / 256, 256>>>(G, 2048, 1024, 1536, Hs, SH, c1);

    mma_gemm<<<dim3(2048 / 128, 4096 / 128), 256, GSMEM>>>(
        Hs, SH, Whh, SWs, G1, nullptr, nullptr, nullptr, 4096, 2048, 512, 1);

    cell_step_kernel<<<BATCH * HID / 4 / 256, 256>>>(G1, c1, Hs, SH);

    // pruned layers (N=1536, gate layout [i|g|o])
    mma_gemm<<<dim3(NPRU / 128, 4096 / 128), 256, GSMEM>>>(
        Hs, SH, W2, SWp, G, b2p, nullptr, nullptr, 4096, NPRU, 512, 0);
    cell_zero_kernel<<<BATCH * HID / 4 / 256, 256>>>(G, NPRU, 512, 1024, Hs, SH, nullptr);

    mma_gemm<<<dim3(NPRU / 128, 4096 / 128), 256, GSMEM>>>(
        Hs, SH, W3, SWp, G, b3p, nullptr, nullptr, 4096, NPRU, 512, 0);
    cell_zero_kernel<<<BATCH * HID / 4 / 256, 256>>>(G, NPRU, 512, 1024, Hs, SH, nullptr);

    mma_gemm<<<dim3(NPRU / 128, 4096 / 128), 256, GSMEM>>>(
        Hs, SH, W4, SWp, G, b4p, nullptr, nullptr, 4096, NPRU, 512, 0);
    cell_zero_kernel<<<BATCH * HID / 4 / 256, 256>>>(G, NPRU, 512, 1024, Hs, SH, nullptr);

    // head: out = (u < relu(h4 @ Wout^T + bout))
    mma_gemm<<<dim3(512 / 128, 4096 / 128), 256, GSMEM>>>(
        Hs, SH, Wo, SWo, nullptr, bout, u, out, 4096, 512, 512, 2);
}